// round 8
// baseline (speedup 1.0000x reference)
#include <cuda_runtime.h>

#define DD 128
#define E_MAX 800000
#define R_MAX 512
#define SPLIT 8
#define SCHUNK 4096

// ---- scratch (device globals; no allocation allowed) ----
__device__ int   g_off[R_MAX + 1];
__device__ int   g_cursor[R_MAX];
__device__ int4  g_edges[E_MAX];           // sorted {src, dst, scale_bits, pad}
__device__ float g_Whi[2 * 256 * 128];     // stacked [loop_w; time_w], tf32 hi
__device__ float g_Wlo[2 * 256 * 128];     // tf32 lo

#define REDV4(ptr, v)                                                   \
    asm volatile("red.global.add.v4.f32 [%0], {%1,%2,%3,%4};"           \
                 :: "l"(ptr), "f"((v).x), "f"((v).y), "f"((v).z), "f"((v).w) \
                 : "memory")

#define REDV2(ptr, a, b)                                                \
    asm volatile("red.global.add.v2.f32 [%0], {%1,%2};"                 \
                 :: "l"(ptr), "f"(a), "f"(b) : "memory")

#define MMA_TF32(c, a, b)                                               \
    asm volatile("mma.sync.aligned.m16n8k8.row.col.f32.tf32.tf32.f32 "  \
                 "{%0,%1,%2,%3}, {%4,%5,%6,%7}, {%8,%9}, {%0,%1,%2,%3};" \
                 : "+f"((c)[0]), "+f"((c)[1]), "+f"((c)[2]), "+f"((c)[3]) \
                 : "r"((a)[0]), "r"((a)[1]), "r"((a)[2]), "r"((a)[3]),  \
                   "r"((b)[0]), "r"((b)[1]))

__device__ __forceinline__ unsigned f2tf32(float v)
{
    unsigned r;
    asm("cvt.rna.tf32.f32 %0, %1;" : "=r"(r) : "f"(v));
    return r;
}

// smem layout (floats), dense role: AsHi[128][36] AsLo[128][36] WsHi[32][68] WsLo[32][68]
#define AS_STRIDE 36
#define WS_STRIDE 68
#define OFF_ASLO (128 * AS_STRIDE)
#define OFF_WSHI (2 * 128 * AS_STRIDE)
#define OFF_WSLO (2 * 128 * AS_STRIDE + 32 * WS_STRIDE)
#define FUSED_SMEM_FLOATS (2 * 128 * AS_STRIDE + 2 * 32 * WS_STRIDE)

// ---------------------------------------------------------------------------
// Weight split: W' = [loop_w; time_w] (256x128) -> tf32 hi/lo, both layers.
// ---------------------------------------------------------------------------
__global__ void split_w_kernel(const float* __restrict__ lw1,
                               const float* __restrict__ tw1,
                               const float* __restrict__ lw2,
                               const float* __restrict__ tw2)
{
    int idx = blockIdx.x * blockDim.x + threadIdx.x;
    if (idx >= 2 * 256 * 128) return;
    int layer = idx >> 15;
    int k = (idx >> 7) & 255;
    int n = idx & 127;
    const float* lw = layer ? lw2 : lw1;
    const float* tw = layer ? tw2 : tw1;
    float v = (k < 128) ? lw[k * 128 + n] : tw[(k - 128) * 128 + n];
    unsigned hb = f2tf32(v);
    float lo = v - __uint_as_float(hb);
    g_Whi[idx] = __uint_as_float(hb);
    g_Wlo[idx] = __uint_as_float(f2tf32(lo));
}

// ---------------------------------------------------------------------------
// Fused layer kernel: dense (tensor-core 3xTF32) + edge (L2 red) roles run
// concurrently; output pre-zeroed, ALL writes are commutative red.adds.
//   i % F == 0 -> dense block db = i/F: tile row (db>>1)*128, n-half db&1
//   else       -> edge slot j = (i/F)*(F-1) + i%F - 1: type j%R, split j/R
// ---------------------------------------------------------------------------
__global__ __launch_bounds__(256, 2)
void fused_layer_kernel(const float* __restrict__ h,
                        const float* __restrict__ prev,
                        const float* __restrict__ time_diff,
                        const float* __restrict__ W,
                        float* __restrict__ out,
                        int N, int R, int F, int layer)
{
    extern __shared__ float sm[];
    const int i = blockIdx.x;

    if ((i % F) == 0) {
        // ================= dense role (M=128 x N=64 tile) =================
        float* AsHi = sm;
        float* AsLo = sm + OFF_ASLO;
        float* WsHi = sm + OFF_WSHI;
        float* WsLo = sm + OFF_WSLO;

        const int db = i / F;
        const int rowTile = (db >> 1) * 128;
        const int nhalf = db & 1;

        const float* whi = g_Whi + layer * 32768;
        const float* wlo = g_Wlo + layer * 32768;

        const int tid  = threadIdx.x;
        const int wid  = tid >> 5;
        const int lane = tid & 31;
        const int g = lane >> 2;
        const int t = lane & 3;
        const int mbase = (wid & 3) * 32;
        const int nbase = (wid >> 2) * 32;

        const int sr  = tid >> 1;
        const int sc0 = (tid & 1) * 16;
        const int snode = rowTile + sr;
        const bool sok = (snode < N);
        const float dec = sok ? __expf(-__ldg(time_diff + snode) * 0.1f) : 0.f;

        const int wr  = tid >> 3;          // 0..31
        const int wc  = (tid & 7) * 8;     // 0..56

        float acc[2][4][4];
#pragma unroll
        for (int mi = 0; mi < 2; mi++)
#pragma unroll
            for (int nt = 0; nt < 4; nt++)
#pragma unroll
                for (int c = 0; c < 4; c++) acc[mi][nt][c] = 0.f;

#pragma unroll 1
        for (int kc = 0; kc < 8; kc++) {
            __syncthreads();
            // ---- stage A (fp32 -> tf32 hi/lo), register-light ----
            {
                const float* src = (kc < 4)
                    ? (h    + (size_t)snode * DD + kc * 32 + sc0)
                    : (prev + (size_t)snode * DD + (kc - 4) * 32 + sc0);
                float* dhi = AsHi + sr * AS_STRIDE + sc0;
                float* dlo = AsLo + sr * AS_STRIDE + sc0;
#pragma unroll
                for (int j = 0; j < 4; j++) {
                    float4 v = sok ? __ldg((const float4*)src + j)
                                   : make_float4(0.f, 0.f, 0.f, 0.f);
                    if (kc >= 4) { v.x *= dec; v.y *= dec; v.z *= dec; v.w *= dec; }
                    float4 hi, lo;
                    hi.x = __uint_as_float(f2tf32(v.x));
                    hi.y = __uint_as_float(f2tf32(v.y));
                    hi.z = __uint_as_float(f2tf32(v.z));
                    hi.w = __uint_as_float(f2tf32(v.w));
                    lo.x = __uint_as_float(f2tf32(v.x - hi.x));
                    lo.y = __uint_as_float(f2tf32(v.y - hi.y));
                    lo.z = __uint_as_float(f2tf32(v.z - hi.z));
                    lo.w = __uint_as_float(f2tf32(v.w - hi.w));
                    ((float4*)dhi)[j] = hi;
                    ((float4*)dlo)[j] = lo;
                }
            }
            // ---- stage W half (already split; straight copy) ----
            {
                const float* shi = whi + (kc * 32 + wr) * 128 + nhalf * 64 + wc;
                const float* slo = wlo + (kc * 32 + wr) * 128 + nhalf * 64 + wc;
                float* dhi = WsHi + wr * WS_STRIDE + wc;
                float* dlo = WsLo + wr * WS_STRIDE + wc;
                ((float4*)dhi)[0] = __ldg((const float4*)shi + 0);
                ((float4*)dhi)[1] = __ldg((const float4*)shi + 1);
                ((float4*)dlo)[0] = __ldg((const float4*)slo + 0);
                ((float4*)dlo)[1] = __ldg((const float4*)slo + 1);
            }
            __syncthreads();

#pragma unroll
            for (int ks = 0; ks < 4; ks++) {
                const int k0 = ks * 8;
                unsigned ahi[2][4], alo[2][4];
#pragma unroll
                for (int mi = 0; mi < 2; mi++) {
                    int r0 = (mbase + mi * 16 + g) * AS_STRIDE + k0 + t;
                    int r1 = r0 + 8 * AS_STRIDE;
                    ahi[mi][0] = __float_as_uint(AsHi[r0]);
                    ahi[mi][1] = __float_as_uint(AsHi[r1]);
                    ahi[mi][2] = __float_as_uint(AsHi[r0 + 4]);
                    ahi[mi][3] = __float_as_uint(AsHi[r1 + 4]);
                    alo[mi][0] = __float_as_uint(AsLo[r0]);
                    alo[mi][1] = __float_as_uint(AsLo[r1]);
                    alo[mi][2] = __float_as_uint(AsLo[r0 + 4]);
                    alo[mi][3] = __float_as_uint(AsLo[r1 + 4]);
                }
                unsigned bhi[4][2], blo[4][2];
#pragma unroll
                for (int nt = 0; nt < 4; nt++) {
                    int col = nbase + nt * 8 + g;
                    int i0 = (k0 + t) * WS_STRIDE + col;
                    int i1 = i0 + 4 * WS_STRIDE;
                    bhi[nt][0] = __float_as_uint(WsHi[i0]);
                    bhi[nt][1] = __float_as_uint(WsHi[i1]);
                    blo[nt][0] = __float_as_uint(WsLo[i0]);
                    blo[nt][1] = __float_as_uint(WsLo[i1]);
                }
#pragma unroll
                for (int mi = 0; mi < 2; mi++)
#pragma unroll
                    for (int nt = 0; nt < 4; nt++) {
                        MMA_TF32(acc[mi][nt], ahi[mi], bhi[nt]);
                        MMA_TF32(acc[mi][nt], ahi[mi], blo[nt]);
                        MMA_TF32(acc[mi][nt], alo[mi], bhi[nt]);
                    }
            }
        }

        // ---- epilogue: red.v2 into pre-zeroed output ----
#pragma unroll
        for (int mi = 0; mi < 2; mi++) {
            int row0 = rowTile + mbase + mi * 16 + g;
            int row1 = row0 + 8;
#pragma unroll
            for (int nt = 0; nt < 4; nt++) {
                int col = nhalf * 64 + nbase + nt * 8 + 2 * t;
                if (row0 < N)
                    REDV2(out + (size_t)row0 * DD + col,
                          acc[mi][nt][0], acc[mi][nt][1]);
                if (row1 < N)
                    REDV2(out + (size_t)row1 * DD + col,
                          acc[mi][nt][2], acc[mi][nt][3]);
            }
        }
    } else {
        // ================= edge role (R5 2-wide, known good) =================
        const int j = (i / F) * (F - 1) + (i % F) - 1;
        const int t = j % R;
        const int bsplit = j / R;
        if (bsplit >= SPLIT) return;

        const int lane = threadIdx.x & 31;
        const int warp = threadIdx.x >> 5;

        const int start = g_off[t];
        const int end   = g_off[t + 1];
        if (start >= end) return;

        const float4* wp = (const float4*)(W + (size_t)t * 512) + lane * 4;
        const float4 w0 = __ldg(wp + 0);
        const float4 w1 = __ldg(wp + 1);
        const float4 w2 = __ldg(wp + 2);
        const float4 w3 = __ldg(wp + 3);

        const int stride = 8 * SPLIT;
        int e = start + bsplit * 8 + warp;

        for (; e + stride < end; e += 2 * stride) {
            const int4 mdA = __ldg(g_edges + e);
            const int4 mdB = __ldg(g_edges + e + stride);

            float4 hA = __ldg((const float4*)(h + (size_t)mdA.x * DD) + lane);
            float4 hB = __ldg((const float4*)(h + (size_t)mdB.x * DD) + lane);

            const float scA = __int_as_float(mdA.z);
            const float scB = __int_as_float(mdB.z);

            float4 mA, mB;
            mA.x = hA.x * w0.x + hA.y * w1.x + hA.z * w2.x + hA.w * w3.x;
            mA.y = hA.x * w0.y + hA.y * w1.y + hA.z * w2.y + hA.w * w3.y;
            mA.z = hA.x * w0.z + hA.y * w1.z + hA.z * w2.z + hA.w * w3.z;
            mA.w = hA.x * w0.w + hA.y * w1.w + hA.z * w2.w + hA.w * w3.w;
            mB.x = hB.x * w0.x + hB.y * w1.x + hB.z * w2.x + hB.w * w3.x;
            mB.y = hB.x * w0.y + hB.y * w1.y + hB.z * w2.y + hB.w * w3.y;
            mB.z = hB.x * w0.z + hB.y * w1.z + hB.z * w2.z + hB.w * w3.z;
            mB.w = hB.x * w0.w + hB.y * w1.w + hB.z * w2.w + hB.w * w3.w;
            mA.x *= scA; mA.y *= scA; mA.z *= scA; mA.w *= scA;
            mB.x *= scB; mB.y *= scB; mB.z *= scB; mB.w *= scB;

            REDV4(out + (size_t)mdA.y * DD + lane * 4, mA);
            REDV4(out + (size_t)mdB.y * DD + lane * 4, mB);
        }

        if (e < end) {
            const int4 md = __ldg(g_edges + e);
            float4 hv = __ldg((const float4*)(h + (size_t)md.x * DD) + lane);
            const float sc = __int_as_float(md.z);

            float4 m;
            m.x = hv.x * w0.x + hv.y * w1.x + hv.z * w2.x + hv.w * w3.x;
            m.y = hv.x * w0.y + hv.y * w1.y + hv.z * w2.y + hv.w * w3.y;
            m.z = hv.x * w0.z + hv.y * w1.z + hv.z * w2.z + hv.w * w3.z;
            m.w = hv.x * w0.w + hv.y * w1.w + hv.z * w2.w + hv.w * w3.w;
            m.x *= sc; m.y *= sc; m.z *= sc; m.w *= sc;

            REDV4(out + (size_t)md.y * DD + lane * 4, m);
        }
    }
}

// ---------------------------------------------------------------------------
// Sort pipeline + utilities.
// ---------------------------------------------------------------------------
__global__ void zero_out_kernel(float4* __restrict__ p, int n4)
{
    int i = blockIdx.x * blockDim.x + threadIdx.x;
    if (i < n4) p[i] = make_float4(0.f, 0.f, 0.f, 0.f);
}

__global__ void zero_kernel(int R)
{
    int i = blockIdx.x * blockDim.x + threadIdx.x;
    if (i <= R) g_off[i] = 0;
    if (i < R)  g_cursor[i] = 0;
}

__global__ __launch_bounds__(256)
void hist_kernel(const int* __restrict__ etyp, int E, int R)
{
    __shared__ int lh[R_MAX];
    for (int i = threadIdx.x; i < R; i += blockDim.x) lh[i] = 0;
    __syncthreads();
    for (int e = blockIdx.x * blockDim.x + threadIdx.x; e < E;
         e += gridDim.x * blockDim.x)
        atomicAdd(&lh[__ldg(etyp + e)], 1);
    __syncthreads();
    for (int i = threadIdx.x; i < R; i += blockDim.x) {
        int v = lh[i];
        if (v) atomicAdd(&g_off[i + 1], v);
    }
}

__global__ __launch_bounds__(512)
void scan_kernel(int R)
{
    __shared__ int buf[512];
    const int tid = threadIdx.x;
    buf[tid] = (tid <= R) ? g_off[tid] : 0;
    __syncthreads();
#pragma unroll
    for (int d = 1; d < 512; d <<= 1) {
        int v = (tid >= d) ? buf[tid - d] : 0;
        __syncthreads();
        buf[tid] += v;
        __syncthreads();
    }
    if (tid <= R) g_off[tid] = buf[tid];
}

__global__ __launch_bounds__(256)
void scatter_kernel(const int* __restrict__ esrc,
                    const int* __restrict__ edst,
                    const int* __restrict__ etyp,
                    const float* __restrict__ enorm,
                    const float* __restrict__ nnorm,
                    int E, int R)
{
    __shared__ int lbase[R_MAX];
    __shared__ int lcur[R_MAX];

    const int e0 = blockIdx.x * SCHUNK;
    const int e1 = min(e0 + SCHUNK, E);

    for (int i = threadIdx.x; i < R; i += blockDim.x) {
        lbase[i] = 0;
        lcur[i]  = 0;
    }
    __syncthreads();

    for (int e = e0 + threadIdx.x; e < e1; e += blockDim.x)
        atomicAdd(&lbase[__ldg(etyp + e)], 1);
    __syncthreads();

    for (int i = threadIdx.x; i < R; i += blockDim.x) {
        int cnt = lbase[i];
        lbase[i] = cnt ? (g_off[i] + atomicAdd(&g_cursor[i], cnt)) : 0;
    }
    __syncthreads();

    for (int e = e0 + threadIdx.x; e < e1; e += blockDim.x) {
        int t = __ldg(etyp + e);
        int d = __ldg(edst + e);
        int pos = lbase[t] + atomicAdd(&lcur[t], 1);
        float sc = __ldg(enorm + e) * __ldg(nnorm + d);
        g_edges[pos] = make_int4(__ldg(esrc + e), d, __float_as_int(sc), 0);
    }
}

__global__ void relu_kernel(float* __restrict__ x, int n)
{
    int i = blockIdx.x * blockDim.x + threadIdx.x;
    if (i < n) {
        float v = x[i];
        x[i] = v > 0.f ? v : 0.f;
    }
}

extern "C" void kernel_launch(void* const* d_in, const int* in_sizes, int n_in,
                              void* d_out, int out_size)
{
    const float* h   = (const float*)d_in[0];
    const float* fp  = (const float*)d_in[1];
    const float* sp  = (const float*)d_in[2];
    const float* td  = (const float*)d_in[3];
    const int*   es  = (const int*)  d_in[4];
    const int*   ed  = (const int*)  d_in[5];
    const int*   et  = (const int*)  d_in[6];
    const float* en  = (const float*)d_in[7];
    const float* nn  = (const float*)d_in[8];
    const float* W1  = (const float*)d_in[9];
    const float* W2  = (const float*)d_in[10];
    const float* lw1 = (const float*)d_in[11];
    const float* lw2 = (const float*)d_in[12];
    const float* tw1 = (const float*)d_in[13];
    const float* tw2 = (const float*)d_in[14];

    const int N = in_sizes[3];            // time_diff is (N,1)
    const int E = in_sizes[4];            // edge_src is (E,)
    const int R = in_sizes[9] / 512;      // W1 is (R, 512)

    float* h1 = (float*)d_out;
    float* h2 = h1 + (size_t)N * DD;

    const int D_BLOCKS = ((N + 127) / 128) * 2;      // 2 n-halves per row tile
    const int E_BLOCKS = R * SPLIT;
    const int F = 1 + (E_BLOCKS + D_BLOCKS - 1) / D_BLOCKS;
    const int T_BLOCKS = D_BLOCKS * F;

    const int scatterBlocks = (E + SCHUNK - 1) / SCHUNK;
    const int fusedSmem = FUSED_SMEM_FLOATS * sizeof(float);
    const int n4 = N * DD / 4;

    cudaFuncSetAttribute(fused_layer_kernel,
                         cudaFuncAttributeMaxDynamicSharedMemorySize,
                         fusedSmem);

    // ---- prep: zero outputs, split weights, counting sort ----
    zero_out_kernel<<<(2 * n4 + 255) / 256, 256>>>((float4*)d_out, 2 * n4);
    split_w_kernel <<<(2 * 256 * 128 + 255) / 256, 256>>>(lw1, tw1, lw2, tw2);
    zero_kernel    <<<(R + 256) / 256, 256>>>(R);
    hist_kernel    <<<256, 256>>>(et, E, R);
    scan_kernel    <<<1, 512>>>(R);
    scatter_kernel <<<scatterBlocks, 256>>>(es, ed, et, en, nn, E, R);

    // ---- layer 1: dense + edge concurrent ----
    fused_layer_kernel<<<T_BLOCKS, 256, fusedSmem>>>(h, fp, td, W1, h1, N, R, F, 0);

    // ---- layer 2 ----
    fused_layer_kernel<<<T_BLOCKS, 256, fusedSmem>>>(h1, sp, td, W2, h2, N, R, F, 1);
    relu_kernel<<<((size_t)N * DD + 255) / 256, 256>>>(h2, N * DD);
}